// round 16
// baseline (speedup 1.0000x reference)
#include <cuda_runtime.h>
#include <cuda_bf16.h>
#include <mma.h>
#include <math.h>
#include <stdint.h>

using namespace nvcuda;

// ---------------------------------------------------------------- constants
#define NR    5120
#define HID   256
#define G4    1024
#define SEQ   30
#define INP   100
#define BATCH 512
#define XW    320         // packed x panel width (3*100 + 20 pad)
#define KTOT  1088        // 320 (x zones) + 768 (h zones)
#define NCH   17          // K chunks of 64
#define ASTR  72          // A smem row stride (halves)
#define BSTR  72          // B smem row stride (halves) - 64 cols + 8 pad
#define STAGEB (128 * 144 + 64 * 144)   // 18432 + 9216 = 27648
#define SMEM_DYN (2 * STAGEB)           // 55296 -> 3 CTAs/SM (regs permitting)

// ---------------------------------------------------------------- panels
__device__ __align__(16) __nv_bfloat16 g_Apx[(size_t)SEQ * NR * XW];    // [t][n][k]
__device__ __align__(16) __nv_bfloat16 g_Aph[2][(size_t)2 * NR * 768];  // [parity][dir][n][k]
__device__ __align__(16) __nv_bfloat16 g_Bp[(size_t)2 * KTOT * G4];     // [dir][k][col']
__device__ float g_c [(size_t)2 * NR * HID];   // [dir][n][hc]
__device__ float g_hf[(size_t)2 * NR * HID];   // [dir][n][hc]
__device__ float g_bias[2][G4];                // permuted combined bias

// ---------------------------------------------------------------- helpers
__device__ __forceinline__ uint32_t smem_u32(const void* p) {
    return (uint32_t)__cvta_generic_to_shared((void*)p);
}
__device__ __forceinline__ void cpasync16(uint32_t dst, const void* src) {
    asm volatile("cp.async.cg.shared.global [%0], [%1], 16;"
        :: "r"(dst), "l"(__cvta_generic_to_global(src)) : "memory");
}
__device__ __forceinline__ void cpcommit() {
    asm volatile("cp.async.commit_group;" ::: "memory");
}
template<int N> __device__ __forceinline__ void cpwait() {
    asm volatile("cp.async.wait_group %0;" :: "n"(N) : "memory");
}
__device__ __forceinline__ float sigm(float v) {
    return __fdividef(1.f, 1.f + __expf(-v));
}
__device__ __forceinline__ float tanh_(float v) {
    return __fdividef(2.f, 1.f + __expf(-2.f * v)) - 1.f;
}

// ---------------------------------------------------------------- init state + bias (merged)
__global__ void k_init(const float* __restrict__ h0, const float* __restrict__ c0,
                       const float* __restrict__ biF, const float* __restrict__ bhF,
                       const float* __restrict__ biB, const float* __restrict__ bhB) {
    int idx = blockIdx.x * blockDim.x + threadIdx.x;
    if (idx < 2 * G4) {
        int dir = idx >> 10;
        int col = idx & 1023;
        int src = (col & 3) * 256 + (col >> 2);
        g_bias[dir][col] = dir ? (biB[src] + bhB[src]) : (biF[src] + bhF[src]);
    }
    if (idx >= 2 * NR * HID) return;
    int hc = idx & 255;
    size_t r = idx >> 8;          // dir*NR + n
    float h = h0[idx];
    g_c[idx] = c0[idx];
    __nv_bfloat16 hi = __float2bfloat16(h);
    __nv_bfloat16 lo = __float2bfloat16(h - __bfloat162float(hi));
    size_t hb = r * 768;
    g_Aph[0][hb + hc] = hi;
    g_Aph[0][hb + 256 + hc] = hi;
    g_Aph[0][hb + 512 + hc] = lo;
}

// ---------------------------------------------------------------- pack x panel (width 320)
// zones: [0,100) x_hi (pairs Wih_hi), [100,200) x_hi (pairs Wih_lo),
//        [200,300) x_lo (pairs Wih_hi), [300,320) zero
__global__ void k_packx(const float* __restrict__ x) {
    size_t idx = (size_t)blockIdx.x * blockDim.x + threadIdx.x;
    if (idx >= (size_t)SEQ * NR * XW) return;
    int k = idx % XW;
    size_t r = idx / XW;
    int n = r % NR;
    int t = r / NR;
    float w = 0.f;
    bool lo = false;
    if (k < 100)       w = x[((size_t)n * SEQ + t) * INP + k];
    else if (k < 200)  w = x[((size_t)n * SEQ + t) * INP + (k - 100)];
    else if (k < 300) { w = x[((size_t)n * SEQ + t) * INP + (k - 200)]; lo = true; }
    __nv_bfloat16 hi = __float2bfloat16(w);
    g_Apx[idx] = lo ? __float2bfloat16(w - __bfloat162float(hi)) : hi;
}

// ---------------------------------------------------------------- pack B panel (K=1088)
// k zones: [0,100) Wih_hi, [100,200) Wih_lo, [200,300) Wih_hi, [300,320) zero,
//          [320,576) Whh_hi, [576,832) Whh_lo, [832,1088) Whh_hi
// col' = hc*4 + gate; source weight row = gate*256 + hc
__global__ void k_packB(const float* __restrict__ WihF, const float* __restrict__ WhhF,
                        const float* __restrict__ WihB, const float* __restrict__ WhhB) {
    size_t idx = (size_t)blockIdx.x * blockDim.x + threadIdx.x;
    if (idx >= (size_t)2 * KTOT * G4) return;
    int col = idx % G4;
    size_t r = idx / G4;
    int k = r % KTOT;
    int dir = r / KTOT;
    const float* Wih = dir ? WihB : WihF;
    const float* Whh = dir ? WhhB : WhhF;
    int srow = (col & 3) * 256 + (col >> 2);
    float w = 0.f;
    bool lo = false;
    if (k < 100)       w = Wih[srow * INP + k];
    else if (k < 200) { w = Wih[srow * INP + (k - 100)]; lo = true; }
    else if (k < 300)  w = Wih[srow * INP + (k - 200)];
    else if (k < 320)  w = 0.f;
    else if (k < 576)  w = Whh[srow * HID + (k - 320)];
    else if (k < 832) { w = Whh[srow * HID + (k - 576)]; lo = true; }
    else               w = Whh[srow * HID + (k - 832)];
    __nv_bfloat16 hi = __float2bfloat16(w);
    g_Bp[idx] = lo ? __float2bfloat16(w - __bfloat162float(hi)) : hi;
}

// ---------------------------------------------------------------- fused step GEMM + cell update
// grid (16, 40, 2), 128 threads. CTA tile 128M x 64N, warp tile 64x32 (2x2 warps).
// 2-stage cp.async double-buffer; 3 CTAs/SM (regs capped at 170 by launch bounds).
__global__ __launch_bounds__(128, 3) void k_step(int t) {
    extern __shared__ char dyn[];
    __shared__ float sbias[64];

    const int nt = blockIdx.x, mt = blockIdx.y, dir = blockIdx.z;
    const int tx = dir ? (SEQ - 1 - t) : t;
    const int tid = threadIdx.x;
    const int wid = tid >> 5;
    const int wm = wid & 1, wn = wid >> 1;    // 2 x 2 warp grid: wm->64 rows, wn->32 cols
    const int col0 = nt * 64, row0 = mt * 128;

    if (tid < 64) sbias[tid] = g_bias[dir][col0 + tid];

    const __nv_bfloat16* Apx = g_Apx + ((size_t)tx * NR + row0) * XW;
    const __nv_bfloat16* Aph = g_Aph[t & 1] + ((size_t)dir * NR + row0) * 768;
    __nv_bfloat16* AphW      = g_Aph[(t + 1) & 1];
    const __nv_bfloat16* Bp  = g_Bp + (size_t)dir * KTOT * G4;

    wmma::fragment<wmma::accumulator, 16, 16, 16, float> acc[4][2];
#pragma unroll
    for (int i = 0; i < 4; i++)
#pragma unroll
        for (int j = 0; j < 2; j++) wmma::fill_fragment(acc[i][j], 0.f);

    // ---- async fill of one stage ----
    auto issue = [&](int c) {
        int s = c & 1;
        char* As = dyn + s * STAGEB;
        char* Bs = As + 128 * 144;
#pragma unroll
        for (int i = 0; i < 8; i++) {          // A: 128 rows x 64 k (1024 x 16B)
            int u = tid + i * 128;
            int r = u >> 3, kc = u & 7;
            const __nv_bfloat16* src = (c < 5)
                ? Apx + (size_t)r * XW + c * 64 + kc * 8
                : Aph + (size_t)r * 768 + (c - 5) * 64 + kc * 8;
            cpasync16(smem_u32(As + r * 144 + kc * 16), src);
        }
#pragma unroll
        for (int i = 0; i < 4; i++) {          // B: 64 k x 64 cols (512 x 16B, 8 groups/row)
            int u = tid + i * 128;
            int r = u >> 3, nc = u & 7;
            const __nv_bfloat16* src = Bp + (size_t)(c * 64 + r) * G4 + col0 + nc * 8;
            cpasync16(smem_u32(Bs + r * 144 + nc * 16), src);
        }
        cpcommit();
    };

    issue(0);

    for (int c = 0; c < NCH; c++) {
        if (c + 1 < NCH) issue(c + 1);
        if (c + 1 < NCH) cpwait<1>(); else cpwait<0>();
        __syncthreads();

        int s = c & 1;
        const __nv_bfloat16* As = (const __nv_bfloat16*)(dyn + s * STAGEB);
        const __nv_bfloat16* Bs = (const __nv_bfloat16*)(dyn + s * STAGEB + 128 * 144);
#pragma unroll
        for (int kk = 0; kk < 64; kk += 16) {
            wmma::fragment<wmma::matrix_a, 16, 16, 16, __nv_bfloat16, wmma::row_major> a[4];
            wmma::fragment<wmma::matrix_b, 16, 16, 16, __nv_bfloat16, wmma::row_major> b[2];
#pragma unroll
            for (int i = 0; i < 4; i++)
                wmma::load_matrix_sync(a[i], As + (wm * 64 + i * 16) * ASTR + kk, ASTR);
#pragma unroll
            for (int j = 0; j < 2; j++)
                wmma::load_matrix_sync(b[j], Bs + kk * BSTR + wn * 32 + j * 16, BSTR);
#pragma unroll
            for (int i = 0; i < 4; i++)
#pragma unroll
                for (int j = 0; j < 2; j++)
                    wmma::mma_sync(acc[i][j], a[i], b[j], acc[i][j]);
        }
        __syncthreads();                        // stage consumed before re-fill
    }

    // ---- epilogue: C -> smem -> cell update -> h panel / c ----
    float* Cs = (float*)dyn;                    // 128 rows x 68 stride fp32 = 34.8KB
#pragma unroll
    for (int i = 0; i < 4; i++)
#pragma unroll
        for (int j = 0; j < 2; j++)
            wmma::store_matrix_sync(Cs + (wm * 64 + i * 16) * 68 + wn * 32 + j * 16,
                                    acc[i][j], 68, wmma::mem_row_major);
    __syncthreads();

    const int hcl  = tid & 15;                  // local hc within 64-col tile (16 hc)
    const int rblk = tid >> 4;                  // 0..7
    const int hc   = nt * 16 + hcl;
    const bool last = (t == SEQ - 1);
#pragma unroll 4
    for (int i = 0; i < 16; i++) {
        int row = rblk * 16 + i;
        int n = row0 + row;
        const float* cr = Cs + row * 68 + hcl * 4;
        float gi = cr[0] + sbias[hcl * 4 + 0];
        float gf = cr[1] + sbias[hcl * 4 + 1];
        float gg = cr[2] + sbias[hcl * 4 + 2];
        float go = cr[3] + sbias[hcl * 4 + 3];
        size_t ci = ((size_t)dir * NR + n) * HID + hc;
        float c_ = g_c[ci];
        c_ = sigm(gf) * c_ + sigm(gi) * tanh_(gg);
        g_c[ci] = c_;
        float h = sigm(go) * tanh_(c_);
        if (last) g_hf[ci] = h;
        __nv_bfloat16 hi = __float2bfloat16(h);
        __nv_bfloat16 lo = __float2bfloat16(h - __bfloat162float(hi));
        size_t hb = ((size_t)dir * NR + n) * 768;
        AphW[hb + hc] = hi;
        AphW[hb + 256 + hc] = hi;
        AphW[hb + 512 + hc] = lo;
    }
}

// ---------------------------------------------------------------- x_fea assembly
__global__ void k_xfea(float* __restrict__ out_xfea) {
    int idx = blockIdx.x * blockDim.x + threadIdx.x;
    if (idx >= NR * HID) return;
    int k = idx & 255;
    out_xfea[idx] = (k < 128) ? g_hf[idx] : g_hf[(size_t)NR * HID + idx];
}

// ---------------------------------------------------------------- head
__global__ __launch_bounds__(64) void k_head(
    const float* __restrict__ W1, const float* __restrict__ b1,
    const float* __restrict__ W2, const float* __restrict__ b2,
    float* __restrict__ out)
{
    int b = blockIdx.x;
    int u = threadIdx.x;
    const float* __restrict__ flat = out + BATCH * 5 + b * 2560;
    __shared__ float z[64];
    __shared__ float logit[5];

    float acc = b1[u];
    const float* __restrict__ w = W1 + u * 2560;
#pragma unroll 4
    for (int v = 0; v < 2560; v++)
        acc = fmaf(flat[v], w[v], acc);
    z[u] = acc;
    __syncthreads();

    if (u < 5) {
        float a = b2[u];
#pragma unroll
        for (int j = 0; j < 64; j++)
            a = fmaf(z[j], W2[u * 64 + j], a);
        logit[u] = a;
    }
    __syncthreads();

    if (u == 0) {
        float m = logit[0];
#pragma unroll
        for (int p = 1; p < 5; p++) m = fmaxf(m, logit[p]);
        float e[5], s = 0.f;
#pragma unroll
        for (int p = 0; p < 5; p++) { e[p] = expf(logit[p] - m); s += e[p]; }
        float inv = 1.f / s;
#pragma unroll
        for (int p = 0; p < 5; p++) out[b * 5 + p] = e[p] * inv;
    }
}

// ---------------------------------------------------------------- launcher
extern "C" void kernel_launch(void* const* d_in, const int* in_sizes, int n_in,
                              void* d_out, int out_size)
{
    const float* x    = (const float*)d_in[0];
    const float* h0   = (const float*)d_in[1];
    const float* c0   = (const float*)d_in[2];
    const float* WihF = (const float*)d_in[3];
    const float* WhhF = (const float*)d_in[4];
    const float* biF  = (const float*)d_in[5];
    const float* bhF  = (const float*)d_in[6];
    const float* WihB = (const float*)d_in[7];
    const float* WhhB = (const float*)d_in[8];
    const float* biB  = (const float*)d_in[9];
    const float* bhB  = (const float*)d_in[10];
    const float* W1   = (const float*)d_in[11];
    const float* b1   = (const float*)d_in[12];
    const float* W2   = (const float*)d_in[13];
    const float* b2   = (const float*)d_in[14];
    float* out = (float*)d_out;

    cudaFuncSetAttribute(k_step, cudaFuncAttributeMaxDynamicSharedMemorySize, SMEM_DYN);

    // Exactly 3 setup launches -> ncu's captured 4th launch is k_step #1.
    k_init<<<(2 * NR * HID + 255) / 256, 256>>>(h0, c0, biF, bhF, biB, bhB);
    size_t npx = (size_t)SEQ * NR * XW;
    k_packx<<<(unsigned)((npx + 255) / 256), 256>>>(x);
    size_t npb = (size_t)2 * KTOT * G4;
    k_packB<<<(unsigned)((npb + 255) / 256), 256>>>(WihF, WhhF, WihB, WhhB);

    dim3 ggrid(G4 / 64, NR / 128, 2);   // (16, 40, 2) = 1280 CTAs
    for (int t = 0; t < SEQ; t++)
        k_step<<<ggrid, 128, SMEM_DYN>>>(t);

    k_xfea<<<(NR * HID + 255) / 256, 256>>>(out + BATCH * 5);
    k_head<<<BATCH, 64>>>(W1, b1, W2, b2, out);
}

// round 17
// speedup vs baseline: 1.5201x; 1.5201x over previous
#include <cuda_runtime.h>
#include <cuda_bf16.h>
#include <mma.h>
#include <math.h>
#include <stdint.h>

using namespace nvcuda;

// ---------------------------------------------------------------- constants
#define NR    5120
#define HID   256
#define G4    1024
#define SEQ   30
#define INP   100
#define BATCH 512
#define XW    320         // packed x panel width (3*100 + 20 pad)
#define KTOT  1088        // 320 (x zones) + 768 (h zones)
#define NCH   17          // K chunks of 64
#define ASTR  72          // A smem row stride (halves)
#define BSTR  136         // B smem row stride (halves): 128 cols + 8 pad
#define STAGEB (128 * 144 + 64 * 272)   // 18432 + 17408 = 35840
#define SMEM_DYN (3 * STAGEB)           // 107520 -> 2 CTAs/SM

// ---------------------------------------------------------------- panels
__device__ __align__(16) __nv_bfloat16 g_Apx[(size_t)SEQ * NR * XW];    // [t][n][k]
__device__ __align__(16) __nv_bfloat16 g_Aph[2][(size_t)2 * NR * 768];  // [parity][dir][n][k]
__device__ __align__(16) __nv_bfloat16 g_Bp[(size_t)2 * KTOT * G4];     // [dir][k][col']
__device__ float g_c [(size_t)2 * NR * HID];   // [dir][n][hc]
__device__ float g_hf[(size_t)2 * NR * HID];   // [dir][n][hc]
__device__ float g_bias[2][G4];                // permuted combined bias

// ---------------------------------------------------------------- helpers
__device__ __forceinline__ uint32_t smem_u32(const void* p) {
    return (uint32_t)__cvta_generic_to_shared((void*)p);
}
__device__ __forceinline__ void cpasync16(uint32_t dst, const void* src) {
    asm volatile("cp.async.cg.shared.global [%0], [%1], 16;"
        :: "r"(dst), "l"(__cvta_generic_to_global(src)) : "memory");
}
__device__ __forceinline__ void cpcommit() {
    asm volatile("cp.async.commit_group;" ::: "memory");
}
template<int N> __device__ __forceinline__ void cpwait() {
    asm volatile("cp.async.wait_group %0;" :: "n"(N) : "memory");
}
__device__ __forceinline__ float sigm(float v) {
    return __fdividef(1.f, 1.f + __expf(-v));
}
__device__ __forceinline__ float tanh_(float v) {
    return __fdividef(2.f, 1.f + __expf(-2.f * v)) - 1.f;
}

// ---------------------------------------------------------------- init state + bias (merged)
__global__ void k_init(const float* __restrict__ h0, const float* __restrict__ c0,
                       const float* __restrict__ biF, const float* __restrict__ bhF,
                       const float* __restrict__ biB, const float* __restrict__ bhB) {
    int idx = blockIdx.x * blockDim.x + threadIdx.x;
    if (idx < 2 * G4) {
        int dir = idx >> 10;
        int col = idx & 1023;
        int src = (col & 3) * 256 + (col >> 2);
        g_bias[dir][col] = dir ? (biB[src] + bhB[src]) : (biF[src] + bhF[src]);
    }
    if (idx >= 2 * NR * HID) return;
    int hc = idx & 255;
    size_t r = idx >> 8;          // dir*NR + n
    float h = h0[idx];
    g_c[idx] = c0[idx];
    __nv_bfloat16 hi = __float2bfloat16(h);
    __nv_bfloat16 lo = __float2bfloat16(h - __bfloat162float(hi));
    size_t hb = r * 768;
    g_Aph[0][hb + hc] = hi;
    g_Aph[0][hb + 256 + hc] = hi;
    g_Aph[0][hb + 512 + hc] = lo;
}

// ---------------------------------------------------------------- pack x panel (width 320)
// zones: [0,100) x_hi (pairs Wih_hi), [100,200) x_hi (pairs Wih_lo),
//        [200,300) x_lo (pairs Wih_hi), [300,320) zero
__global__ void k_packx(const float* __restrict__ x) {
    size_t idx = (size_t)blockIdx.x * blockDim.x + threadIdx.x;
    if (idx >= (size_t)SEQ * NR * XW) return;
    int k = idx % XW;
    size_t r = idx / XW;
    int n = r % NR;
    int t = r / NR;
    float w = 0.f;
    bool lo = false;
    if (k < 100)       w = x[((size_t)n * SEQ + t) * INP + k];
    else if (k < 200)  w = x[((size_t)n * SEQ + t) * INP + (k - 100)];
    else if (k < 300) { w = x[((size_t)n * SEQ + t) * INP + (k - 200)]; lo = true; }
    __nv_bfloat16 hi = __float2bfloat16(w);
    g_Apx[idx] = lo ? __float2bfloat16(w - __bfloat162float(hi)) : hi;
}

// ---------------------------------------------------------------- pack B panel (K=1088)
// k zones: [0,100) Wih_hi, [100,200) Wih_lo, [200,300) Wih_hi, [300,320) zero,
//          [320,576) Whh_hi, [576,832) Whh_lo, [832,1088) Whh_hi
// col' = hc*4 + gate; source weight row = gate*256 + hc
__global__ void k_packB(const float* __restrict__ WihF, const float* __restrict__ WhhF,
                        const float* __restrict__ WihB, const float* __restrict__ WhhB) {
    size_t idx = (size_t)blockIdx.x * blockDim.x + threadIdx.x;
    if (idx >= (size_t)2 * KTOT * G4) return;
    int col = idx % G4;
    size_t r = idx / G4;
    int k = r % KTOT;
    int dir = r / KTOT;
    const float* Wih = dir ? WihB : WihF;
    const float* Whh = dir ? WhhB : WhhF;
    int srow = (col & 3) * 256 + (col >> 2);
    float w = 0.f;
    bool lo = false;
    if (k < 100)       w = Wih[srow * INP + k];
    else if (k < 200) { w = Wih[srow * INP + (k - 100)]; lo = true; }
    else if (k < 300)  w = Wih[srow * INP + (k - 200)];
    else if (k < 320)  w = 0.f;
    else if (k < 576)  w = Whh[srow * HID + (k - 320)];
    else if (k < 832) { w = Whh[srow * HID + (k - 576)]; lo = true; }
    else               w = Whh[srow * HID + (k - 832)];
    __nv_bfloat16 hi = __float2bfloat16(w);
    g_Bp[idx] = lo ? __float2bfloat16(w - __bfloat162float(hi)) : hi;
}

// ---------------------------------------------------------------- fused step GEMM + cell update
// grid (8, 40, 2), 256 threads. CTA tile 128M x 128N, warp tile 64x32 (2Mx4N warps).
// 3-stage cp.async pipeline, ONE syncthreads per K chunk. 2 CTAs/SM -> 16 warps/SM.
__global__ __launch_bounds__(256, 2) void k_step(int t) {
    extern __shared__ char dyn[];
    __shared__ float sbias[128];

    const int nt = blockIdx.x, mt = blockIdx.y, dir = blockIdx.z;
    const int tx = dir ? (SEQ - 1 - t) : t;
    const int tid = threadIdx.x;
    const int wid = tid >> 5;
    const int wm = wid >> 2, wn = wid & 3;    // 2(M) x 4(N) warps: 64 rows, 32 cols each
    const int col0 = nt * 128, row0 = mt * 128;

    if (tid < 128) sbias[tid] = g_bias[dir][col0 + tid];

    const __nv_bfloat16* Apx = g_Apx + ((size_t)tx * NR + row0) * XW;
    const __nv_bfloat16* Aph = g_Aph[t & 1] + ((size_t)dir * NR + row0) * 768;
    __nv_bfloat16* AphW      = g_Aph[(t + 1) & 1];
    const __nv_bfloat16* Bp  = g_Bp + (size_t)dir * KTOT * G4;

    wmma::fragment<wmma::accumulator, 16, 16, 16, float> acc[4][2];
#pragma unroll
    for (int i = 0; i < 4; i++)
#pragma unroll
        for (int j = 0; j < 2; j++) wmma::fill_fragment(acc[i][j], 0.f);

    // ---- async fill of one stage (256 threads) ----
    auto issue = [&](int c) {
        int s = c % 3;
        char* As = dyn + s * STAGEB;
        char* Bs = As + 128 * 144;
#pragma unroll
        for (int i = 0; i < 4; i++) {          // A: 128 rows x 64 k (1024 x 16B)
            int u = tid + i * 256;
            int r = u >> 3, kc = u & 7;
            const __nv_bfloat16* src = (c < 5)
                ? Apx + (size_t)r * XW + c * 64 + kc * 8
                : Aph + (size_t)r * 768 + (c - 5) * 64 + kc * 8;
            cpasync16(smem_u32(As + r * 144 + kc * 16), src);
        }
#pragma unroll
        for (int i = 0; i < 4; i++) {          // B: 64 k x 128 cols (1024 x 16B)
            int u = tid + i * 256;
            int r = u >> 4, nc = u & 15;
            const __nv_bfloat16* src = Bp + (size_t)(c * 64 + r) * G4 + col0 + nc * 8;
            cpasync16(smem_u32(Bs + r * 272 + nc * 16), src);
        }
        cpcommit();
    };

    issue(0); issue(1);

    for (int c = 0; c < NCH; c++) {
        if (c + 1 < NCH) cpwait<1>(); else cpwait<0>();
        __syncthreads();   // data of chunk c visible; all warps done with chunk c-1
        if (c + 2 < NCH) issue(c + 2);   // stage (c+2)%3 == (c-1)%3, free per the sync

        int s = c % 3;
        const __nv_bfloat16* As = (const __nv_bfloat16*)(dyn + s * STAGEB);
        const __nv_bfloat16* Bs = (const __nv_bfloat16*)(dyn + s * STAGEB + 128 * 144);
#pragma unroll
        for (int kk = 0; kk < 64; kk += 16) {
            wmma::fragment<wmma::matrix_b, 16, 16, 16, __nv_bfloat16, wmma::row_major> b[2];
#pragma unroll
            for (int j = 0; j < 2; j++)
                wmma::load_matrix_sync(b[j], Bs + kk * BSTR + wn * 32 + j * 16, BSTR);
#pragma unroll
            for (int i = 0; i < 4; i++) {
                wmma::fragment<wmma::matrix_a, 16, 16, 16, __nv_bfloat16, wmma::row_major> a;
                wmma::load_matrix_sync(a, As + (wm * 64 + i * 16) * ASTR + kk, ASTR);
#pragma unroll
                for (int j = 0; j < 2; j++)
                    wmma::mma_sync(acc[i][j], a, b[j], acc[i][j]);
            }
        }
    }

    // ---- epilogue: C -> smem -> cell update -> h panel / c ----
    __syncthreads();
    float* Cs = (float*)dyn;                    // 128 rows x 132 stride fp32 = 67.6KB
#pragma unroll
    for (int i = 0; i < 4; i++)
#pragma unroll
        for (int j = 0; j < 2; j++)
            wmma::store_matrix_sync(Cs + (wm * 64 + i * 16) * 132 + wn * 32 + j * 16,
                                    acc[i][j], 132, wmma::mem_row_major);
    __syncthreads();

    const int hcl  = tid & 31;                  // local hc within 128-col tile (32 hc)
    const int rblk = tid >> 5;                  // 0..7
    const int hc   = nt * 32 + hcl;
    const bool last = (t == SEQ - 1);
#pragma unroll 4
    for (int i = 0; i < 16; i++) {
        int row = rblk * 16 + i;
        int n = row0 + row;
        const float* cr = Cs + row * 132 + hcl * 4;
        float gi = cr[0] + sbias[hcl * 4 + 0];
        float gf = cr[1] + sbias[hcl * 4 + 1];
        float gg = cr[2] + sbias[hcl * 4 + 2];
        float go = cr[3] + sbias[hcl * 4 + 3];
        size_t ci = ((size_t)dir * NR + n) * HID + hc;
        float c_ = g_c[ci];
        c_ = sigm(gf) * c_ + sigm(gi) * tanh_(gg);
        g_c[ci] = c_;
        float h = sigm(go) * tanh_(c_);
        if (last) g_hf[ci] = h;
        __nv_bfloat16 hi = __float2bfloat16(h);
        __nv_bfloat16 lo = __float2bfloat16(h - __bfloat162float(hi));
        size_t hb = ((size_t)dir * NR + n) * 768;
        AphW[hb + hc] = hi;
        AphW[hb + 256 + hc] = hi;
        AphW[hb + 512 + hc] = lo;
    }
}

// ---------------------------------------------------------------- x_fea assembly
__global__ void k_xfea(float* __restrict__ out_xfea) {
    int idx = blockIdx.x * blockDim.x + threadIdx.x;
    if (idx >= NR * HID) return;
    int k = idx & 255;
    out_xfea[idx] = (k < 128) ? g_hf[idx] : g_hf[(size_t)NR * HID + idx];
}

// ---------------------------------------------------------------- head
__global__ __launch_bounds__(64) void k_head(
    const float* __restrict__ W1, const float* __restrict__ b1,
    const float* __restrict__ W2, const float* __restrict__ b2,
    float* __restrict__ out)
{
    int b = blockIdx.x;
    int u = threadIdx.x;
    const float* __restrict__ flat = out + BATCH * 5 + b * 2560;
    __shared__ float z[64];
    __shared__ float logit[5];

    float acc = b1[u];
    const float* __restrict__ w = W1 + u * 2560;
#pragma unroll 4
    for (int v = 0; v < 2560; v++)
        acc = fmaf(flat[v], w[v], acc);
    z[u] = acc;
    __syncthreads();

    if (u < 5) {
        float a = b2[u];
#pragma unroll
        for (int j = 0; j < 64; j++)
            a = fmaf(z[j], W2[u * 64 + j], a);
        logit[u] = a;
    }
    __syncthreads();

    if (u == 0) {
        float m = logit[0];
#pragma unroll
        for (int p = 1; p < 5; p++) m = fmaxf(m, logit[p]);
        float e[5], s = 0.f;
#pragma unroll
        for (int p = 0; p < 5; p++) { e[p] = expf(logit[p] - m); s += e[p]; }
        float inv = 1.f / s;
#pragma unroll
        for (int p = 0; p < 5; p++) out[b * 5 + p] = e[p] * inv;
    }
}

// ---------------------------------------------------------------- launcher
extern "C" void kernel_launch(void* const* d_in, const int* in_sizes, int n_in,
                              void* d_out, int out_size)
{
    const float* x    = (const float*)d_in[0];
    const float* h0   = (const float*)d_in[1];
    const float* c0   = (const float*)d_in[2];
    const float* WihF = (const float*)d_in[3];
    const float* WhhF = (const float*)d_in[4];
    const float* biF  = (const float*)d_in[5];
    const float* bhF  = (const float*)d_in[6];
    const float* WihB = (const float*)d_in[7];
    const float* WhhB = (const float*)d_in[8];
    const float* biB  = (const float*)d_in[9];
    const float* bhB  = (const float*)d_in[10];
    const float* W1   = (const float*)d_in[11];
    const float* b1   = (const float*)d_in[12];
    const float* W2   = (const float*)d_in[13];
    const float* b2   = (const float*)d_in[14];
    float* out = (float*)d_out;

    cudaFuncSetAttribute(k_step, cudaFuncAttributeMaxDynamicSharedMemorySize, SMEM_DYN);

    // Exactly 3 setup launches -> ncu's captured 4th launch is k_step #1.
    k_init<<<(2 * NR * HID + 255) / 256, 256>>>(h0, c0, biF, bhF, biB, bhB);
    size_t npx = (size_t)SEQ * NR * XW;
    k_packx<<<(unsigned)((npx + 255) / 256), 256>>>(x);
    size_t npb = (size_t)2 * KTOT * G4;
    k_packB<<<(unsigned)((npb + 255) / 256), 256>>>(WihF, WhhF, WihB, WhhB);

    dim3 ggrid(G4 / 128, NR / 128, 2);   // (8, 40, 2) = 640 CTAs
    for (int t = 0; t < SEQ; t++)
        k_step<<<ggrid, 256, SMEM_DYN>>>(t);

    k_xfea<<<(NR * HID + 255) / 256, 256>>>(out + BATCH * 5);
    k_head<<<BATCH, 64>>>(W1, b1, W2, b2, out);
}